// round 2
// baseline (speedup 1.0000x reference)
#include <cuda_runtime.h>

#define BATCH 64
#define NN 512
#define NDIAG 1023          // number of anti-diagonals (2*512-1)
#define NEGV  (-1e30f)
#define INV_LN2 1.44269504088896340736f
#define LN2F    0.69314718055994530942f
#define TS (NN + 1)         // padded smem row stride (513 -> conflict-free diagonal access)

// Diagonal-major layout: index (k, i) -> k*NN + i, valid i in [max(0,k-511), min(511,k)].
__device__ float g_ddiag[(size_t)BATCH * NDIAG * NN];  // D / ln2, diag layout
__device__ float g_f[(size_t)BATCH * NDIAG * NN];      // forward DP (log2 domain)
__device__ unsigned int g_maxu;                        // order-encoded global max

__device__ __forceinline__ float ex2f(float x) {
    float y; asm("ex2.approx.ftz.f32 %0, %1;" : "=f"(y) : "f"(x)); return y;
}
__device__ __forceinline__ float lg2f(float x) {
    float y; asm("lg2.approx.ftz.f32 %0, %1;" : "=f"(y) : "f"(x)); return y;
}
__device__ __forceinline__ unsigned int fenc(float x) {
    unsigned int b = __float_as_uint(x);
    return (b & 0x80000000u) ? ~b : (b | 0x80000000u);
}
__device__ __forceinline__ float fdec(unsigned int u) {
    return __uint_as_float((u & 0x80000000u) ? (u & 0x7fffffffu) : ~u);
}

__global__ void init_max_kernel() { g_maxu = 0u; }

// ---------------------------------------------------------------------------
// Pre-pass: D (row-major) -> g_ddiag (diagonal-major), scaled by 1/ln2.
// ---------------------------------------------------------------------------
__global__ void __launch_bounds__(256) diagize_kernel(const float* __restrict__ D) {
    __shared__ float t[32][34];
    int b = blockIdx.z, i0 = blockIdx.y * 32, j0 = blockIdx.x * 32;
    const float* Db = D + (size_t)b * NN * NN;
    float* out = g_ddiag + (size_t)b * NDIAG * NN;
    int tid = threadIdx.x, lane = tid & 31, w = tid >> 5;
#pragma unroll
    for (int r = 0; r < 4; r++) {
        int il = w + 8 * r;
        t[il][lane] = Db[(size_t)(i0 + il) * NN + j0 + lane] * INV_LN2;
    }
    __syncthreads();
#pragma unroll
    for (int r = 0; r < 8; r++) {
        int ld = w + 8 * r;           // local diagonal 0..62
        if (ld < 63) {
            int ilo = max(0, ld - 31);
            int il = ilo + lane;
            if (il <= min(31, ld)) {
                int k = i0 + j0 + ld;
                out[(size_t)k * NN + (i0 + il)] = t[il][ld - il];
            }
        }
    }
}

// ---------------------------------------------------------------------------
// LSE cell update (log2 domain): val = d + m + log2(2^(x-m)+2^(y-m)+1)
// ---------------------------------------------------------------------------
__device__ __forceinline__ float lse_cell(float dg, float up, float lf, float dcur) {
    float hi1 = fmaxf(dg, up);
    float lo1 = fminf(dg, up);
    float m   = fmaxf(hi1, lf);
    float o2  = fminf(hi1, lf);
    float s = ex2f(lo1 - m) + ex2f(o2 - m);   // third term is 2^0 = 1
    return dcur + m + lg2f(1.0f + s);
}

// ---------------------------------------------------------------------------
// Forward wavefront DP. One CTA per batch, 512 threads = one per row i.
// ---------------------------------------------------------------------------
__global__ void __launch_bounds__(512) dp_fwd_kernel() {
    int b = blockIdx.x;
    const float* dd = g_ddiag + (size_t)b * NDIAG * NN;
    float* out = g_f + (size_t)b * NDIAG * NN;

    __shared__ float bufs[3][TS];
    float* bc = &bufs[0][1];
    float* b1 = &bufs[1][1];
    float* b2 = &bufs[2][1];

    int i = threadIdx.x;
    if (i == 0) { bufs[0][0] = NEGV; bufs[1][0] = NEGV; bufs[2][0] = NEGV; }
    __syncthreads();

    float pf[8];
#pragma unroll
    for (int q = 0; q < 8; q++) pf[q] = dd[q * NN + i];

    for (int k = 0; k < NDIAG; k++) {
        float dcur = pf[0];
#pragma unroll
        for (int q = 0; q < 7; q++) pf[q] = pf[q + 1];
        {
            int kn = k + 8; if (kn > NDIAG - 1) kn = NDIAG - 1;
            pf[7] = dd[kn * NN + i];
        }

        int j = k - i;
        if (j >= 0 && j < NN) {
            float dg = (j == 0) ? ((i == 0) ? 0.0f : NEGV) : b2[i - 1];
            float up = b1[i - 1];
            float lf = (j == 0) ? NEGV : b1[i];
            float val = lse_cell(dg, up, lf, dcur);
            bc[i] = val;
            out[(size_t)k * NN + i] = val;
        }
        __syncthreads();
        float* tmp = b2; b2 = b1; b1 = bc; bc = tmp;
    }
}

// ---------------------------------------------------------------------------
// Backward wavefront DP fused with combine:
//   - DP on reversed d (via CADDR address mirroring)
//   - logit2 = f2 + b2 - d2 computed on the fly (f prefetched, coalesced)
//   - staged in a 32-diagonal smem tile, flushed row-major to out
//   - global max tracked per-thread -> encoded atomicMax
// Dynamic smem: 3*TS (DP buffers) + 32*TS (logit tile) floats = ~71.8 KB.
// ---------------------------------------------------------------------------
extern __shared__ float sm_bwd[];
__global__ void __launch_bounds__(512) dp_bwd_fused_kernel(float* __restrict__ out) {
    int b = blockIdx.x;
    const float* dd = g_ddiag + (size_t)b * NDIAG * NN;
    const float* fd = g_f + (size_t)b * NDIAG * NN;
    float* ob = out + (size_t)b * NN * NN;

    float* bufs = sm_bwd;               // 3 rows of TS
    float* tile = sm_bwd + 3 * TS;      // 32 rows of TS: tile[kk*TS + i]

    float* bc = bufs + 1;
    float* b1 = bufs + TS + 1;
    float* b2 = bufs + 2 * TS + 1;

    int i = threadIdx.x;
    int lane = i & 31, w = i >> 5;
    if (i == 0) { bufs[0] = NEGV; bufs[TS] = NEGV; bufs[2 * TS] = NEGV; }
    __syncthreads();

    const int CADDR = 1022 * NN + 511;  // reversed addressing

    float pfd[8], pff[8];
#pragma unroll
    for (int q = 0; q < 8; q++) {
        int a = CADDR - (q * NN + i);
        pfd[q] = dd[a];
        pff[q] = fd[a];
    }

    float vmax = -3.4e38f;

    for (int k = 0; k < NDIAG; k++) {
        float dcur = pfd[0];
        float fcur = pff[0];
#pragma unroll
        for (int q = 0; q < 7; q++) { pfd[q] = pfd[q + 1]; pff[q] = pff[q + 1]; }
        {
            int kn = k + 8; if (kn > NDIAG - 1) kn = NDIAG - 1;
            int a = CADDR - (kn * NN + i);
            pfd[7] = dd[a];
            pff[7] = fd[a];
        }

        int j = k - i;            // backward-coords column
        if (j >= 0 && j < NN) {
            float dg = (j == 0) ? ((i == 0) ? 0.0f : NEGV) : b2[i - 1];
            float up = b1[i - 1];
            float lf = (j == 0) ? NEGV : b1[i];
            float val = lse_cell(dg, up, lf, dcur);
            bc[i] = val;
            float lg = fcur + val - dcur;       // logit in log2 domain
            vmax = fmaxf(vmax, lg);
            int kf = 1022 - k;                  // forward diagonal index
            tile[(kf & 31) * TS + (511 - i)] = lg;
        }
        __syncthreads();
        float* tmp = b2; b2 = b1; b1 = bc; bc = tmp;

        if ((k & 31) == 30) {     // kf % 32 == 0 -> group [K0, K0+31] complete
            int K0 = 1022 - k;
            int khi = min(K0 + 31, 1022);
            int rowlo = max(0, K0 - 511);
            int rowhi = min(511, khi);
            for (int r = rowlo + w; r <= rowhi; r += 16) {
                int jlo = max(0, K0 - r);
                int jhi = min(NN - 1, khi - r);
                int j2 = jlo + lane;
                if (j2 <= jhi)
                    ob[(size_t)r * NN + j2] = tile[(r + j2 - K0) * TS + r];
            }
            __syncthreads();      // tile slots reused by next group
        }
    }

    // block max -> encoded atomicMax
#pragma unroll
    for (int o = 16; o > 0; o >>= 1)
        vmax = fmaxf(vmax, __shfl_xor_sync(0xffffffffu, vmax, o));
    if (lane == 0) tile[w] = vmax;
    __syncthreads();
    if (i == 0) {
        float v = tile[0];
#pragma unroll
        for (int q = 1; q < 16; q++) v = fmaxf(v, tile[q]);
        atomicMax(&g_maxu, fenc(v));
    }
}

// ---------------------------------------------------------------------------
// Final: out = (logit2 - max2) * ln2
// ---------------------------------------------------------------------------
__global__ void __launch_bounds__(256) finish_kernel(float* __restrict__ out, int n4) {
    float mx = fdec(g_maxu);
    float4* o4 = (float4*)out;
    int idx = blockIdx.x * blockDim.x + threadIdx.x;
    int stride = gridDim.x * blockDim.x;
    for (int t = idx; t < n4; t += stride) {
        float4 v = o4[t];
        v.x = (v.x - mx) * LN2F;
        v.y = (v.y - mx) * LN2F;
        v.z = (v.z - mx) * LN2F;
        v.w = (v.w - mx) * LN2F;
        o4[t] = v;
    }
}

extern "C" void kernel_launch(void* const* d_in, const int* in_sizes, int n_in,
                              void* d_out, int out_size) {
    const float* d = (const float*)d_in[0];
    float* out = (float*)d_out;

    static const size_t BWD_SMEM = (size_t)(3 + 32) * TS * sizeof(float);
    cudaFuncSetAttribute(dp_bwd_fused_kernel,
                         cudaFuncAttributeMaxDynamicSharedMemorySize, (int)BWD_SMEM);

    init_max_kernel<<<1, 1>>>();

    dim3 dgrid(16, 16, BATCH);
    diagize_kernel<<<dgrid, 256>>>(d);

    dp_fwd_kernel<<<BATCH, 512>>>();

    dp_bwd_fused_kernel<<<BATCH, 512, BWD_SMEM>>>(out);

    finish_kernel<<<4096, 256>>>(out, out_size / 4);
}

// round 3
// speedup vs baseline: 2.9606x; 2.9606x over previous
#include <cuda_runtime.h>

#define BATCH 64
#define NN 512
#define NDIAG 1023          // number of anti-diagonals (2*512-1)
#define NEGV  (-1e30f)
#define INV_LN2 1.44269504088896340736f
#define LN2F    0.69314718055994530942f
#define TS (NN + 1)

// Diagonal-major layout: (k, i) -> k*NN + i, valid i in [max(0,k-511), min(511,k)].
__device__ float g_ddiag[(size_t)BATCH * NDIAG * NN];  // D / ln2, diag layout
__device__ float g_f[(size_t)BATCH * NDIAG * NN];      // forward DP (log2 domain)
__device__ float g_b[(size_t)BATCH * NDIAG * NN];      // backward DP (reversed coords)
__device__ unsigned int g_maxu;                        // order-encoded global max

__device__ __forceinline__ float ex2f(float x) {
    float y; asm("ex2.approx.ftz.f32 %0, %1;" : "=f"(y) : "f"(x)); return y;
}
__device__ __forceinline__ float lg2f(float x) {
    float y; asm("lg2.approx.ftz.f32 %0, %1;" : "=f"(y) : "f"(x)); return y;
}
__device__ __forceinline__ unsigned int fenc(float x) {
    unsigned int b = __float_as_uint(x);
    return (b & 0x80000000u) ? ~b : (b | 0x80000000u);
}
__device__ __forceinline__ float fdec(unsigned int u) {
    return __uint_as_float((u & 0x80000000u) ? (u & 0x7fffffffu) : ~u);
}

__global__ void init_max_kernel() { g_maxu = 0u; }

// ---------------------------------------------------------------------------
// Pre-pass: D (row-major) -> g_ddiag (diagonal-major), scaled by 1/ln2.
// ---------------------------------------------------------------------------
__global__ void __launch_bounds__(256) diagize_kernel(const float* __restrict__ D) {
    __shared__ float t[32][34];
    int b = blockIdx.z, i0 = blockIdx.y * 32, j0 = blockIdx.x * 32;
    const float* Db = D + (size_t)b * NN * NN;
    float* out = g_ddiag + (size_t)b * NDIAG * NN;
    int tid = threadIdx.x, lane = tid & 31, w = tid >> 5;
#pragma unroll
    for (int r = 0; r < 4; r++) {
        int il = w + 8 * r;
        t[il][lane] = Db[(size_t)(i0 + il) * NN + j0 + lane] * INV_LN2;
    }
    __syncthreads();
#pragma unroll
    for (int r = 0; r < 8; r++) {
        int ld = w + 8 * r;
        if (ld < 63) {
            int ilo = max(0, ld - 31);
            int il = ilo + lane;
            if (il <= min(31, ld)) {
                int k = i0 + j0 + ld;
                out[(size_t)k * NN + (i0 + il)] = t[il][ld - il];
            }
        }
    }
}

__device__ __forceinline__ float lse_cell(float dg, float up, float lf, float dcur) {
    float hi1 = fmaxf(dg, up);
    float lo1 = fminf(dg, up);
    float m   = fmaxf(hi1, lf);
    float o2  = fminf(hi1, lf);
    float s = ex2f(lo1 - m) + ex2f(o2 - m);   // third term is 2^0 = 1
    return dcur + m + lg2f(1.0f + s);
}

// ---------------------------------------------------------------------------
// Wavefront DP, one CTA per (batch, direction). 512 threads = one per row i.
// k-loop unrolled x8 so the 8-deep LDG prefetch pipeline is real: pf[p] is
// statically indexed per phase, giving each load 8 diagonals to complete.
// 4 rotating smem buffers: selector k&3 == p&3 is compile-time static.
// ---------------------------------------------------------------------------
__global__ void __launch_bounds__(512) dp_kernel() {
    int bx = blockIdx.x;
    int b = bx >> 1, dir = bx & 1;
    const float* dd = g_ddiag + (size_t)b * NDIAG * NN;
    float* out = (dir ? g_b : g_f) + (size_t)b * NDIAG * NN;

    __shared__ float bufs[4][TS];   // slot [x][0] is the i=-1 boundary (NEG)
    int i = threadIdx.x;
    if (i < 4) bufs[i][0] = NEGV;
    __syncthreads();

    const int CADDR = 1022 * NN + 511;  // bwd: addr = CADDR - (k*NN + i)

    float pf[8];
#pragma unroll
    for (int q = 0; q < 8; q++) {
        int base = q * NN + i;
        pf[q] = dd[dir ? (CADDR - base) : base];
    }

    for (int t = 0; t < 128; t++) {
#pragma unroll
        for (int p = 0; p < 8; p++) {
            int k = t * 8 + p;                 // 0..1023; k==1023 is a no-op pad
            float dcur = pf[p];
            {
                int kn = k + 8; if (kn > NDIAG - 1) kn = NDIAG - 1;
                int base = kn * NN + i;
                pf[p] = dd[dir ? (CADDR - base) : base];
            }
            if (k < NDIAG) {                   // uniform branch
                float* bc  = &bufs[p & 3][1];          // diag k
                float* b1p = &bufs[(p + 3) & 3][1];    // diag k-1
                float* b2p = &bufs[(p + 2) & 3][1];    // diag k-2
                int j = k - i;
                if (j >= 0 && j < NN) {
                    float dg = (j == 0) ? ((i == 0) ? 0.0f : NEGV) : b2p[i - 1];
                    float up = b1p[i - 1];             // i==0 -> boundary = NEG
                    float lf = (j == 0) ? NEGV : b1p[i];
                    float val = lse_cell(dg, up, lf, dcur);
                    bc[i] = val;
                    out[(size_t)k * NN + i] = val;
                }
                __syncthreads();
            }
        }
    }
}

// ---------------------------------------------------------------------------
// Combine: logit2 = f2 + b2 - d2, de-diagonalize to row-major out,
// per-block max -> encoded atomicMax. CTA = (32-diagonal block, batch).
// ---------------------------------------------------------------------------
__global__ void __launch_bounds__(256) combine_kernel(float* __restrict__ out) {
    __shared__ float tile[32][257];
    __shared__ float smax[8];
    int b = blockIdx.y;
    int k0 = blockIdx.x * 32;
    const float* fd = g_f + (size_t)b * NDIAG * NN;
    const float* bd = g_b + (size_t)b * NDIAG * NN;
    const float* dd = g_ddiag + (size_t)b * NDIAG * NN;
    float* ob = out + (size_t)b * NN * NN;
    int tid = threadIdx.x, lane = tid & 31, w = tid >> 5;
    float vmax = -3.4e38f;

    for (int ih = 0; ih < 2; ih++) {
        int ibase = ih * 256;
        for (int kk = 0; kk < 32; kk++) {
            int k = k0 + kk;
            int i = ibase + tid;
            int j = k - i;
            float v = 0.0f;
            if (j >= 0 && j < NN) {
                int a = k * NN + i;
                v = fd[a] + bd[(1022 - k) * NN + (511 - i)] - dd[a];
                vmax = fmaxf(vmax, v);
            }
            tile[kk][tid] = v;
        }
        __syncthreads();
        for (int rr = 0; rr < 32; rr++) {
            int i = ibase + w * 32 + rr;
            int jlo = max(0, k0 - i);
            int jhi = min(NN - 1, k0 + 31 - i);
            int j = jlo + lane;
            if (j <= jhi) {
                int kk = i + j - k0;
                ob[(size_t)i * NN + j] = tile[kk][i - ibase];
            }
        }
        __syncthreads();
    }

#pragma unroll
    for (int o = 16; o > 0; o >>= 1)
        vmax = fmaxf(vmax, __shfl_xor_sync(0xffffffffu, vmax, o));
    if (lane == 0) smax[w] = vmax;
    __syncthreads();
    if (tid == 0) {
        float v = smax[0];
#pragma unroll
        for (int q = 1; q < 8; q++) v = fmaxf(v, smax[q]);
        atomicMax(&g_maxu, fenc(v));
    }
}

// ---------------------------------------------------------------------------
// Final: out = (logit2 - max2) * ln2
// ---------------------------------------------------------------------------
__global__ void __launch_bounds__(256) finish_kernel(float* __restrict__ out, int n4) {
    float mx = fdec(g_maxu);
    float4* o4 = (float4*)out;
    int idx = blockIdx.x * blockDim.x + threadIdx.x;
    int stride = gridDim.x * blockDim.x;
    for (int t = idx; t < n4; t += stride) {
        float4 v = o4[t];
        v.x = (v.x - mx) * LN2F;
        v.y = (v.y - mx) * LN2F;
        v.z = (v.z - mx) * LN2F;
        v.w = (v.w - mx) * LN2F;
        o4[t] = v;
    }
}

extern "C" void kernel_launch(void* const* d_in, const int* in_sizes, int n_in,
                              void* d_out, int out_size) {
    const float* d = (const float*)d_in[0];
    float* out = (float*)d_out;

    init_max_kernel<<<1, 1>>>();

    dim3 dgrid(16, 16, BATCH);
    diagize_kernel<<<dgrid, 256>>>(d);

    dp_kernel<<<BATCH * 2, 512>>>();

    dim3 cgrid(32, BATCH);
    combine_kernel<<<cgrid, 256>>>(out);

    finish_kernel<<<4096, 256>>>(out, out_size / 4);
}